// round 3
// baseline (speedup 1.0000x reference)
#include <cuda_runtime.h>
#include <cuda_bf16.h>
#include <cstdint>

// CrossPatchModule closed form:
//   B=4, C=64, H=W=512, PH=PW=8, PN=64, kh=kw=64
//   ph=h>>6, i=h&63, pw=w>>6, j=w&63
//   s = ph*8+pw;  m=(c+s)&63
//   out[b,c,h,w] = x[b,c, (m>>3)*64 + i, (m&7)*64 + j] + abs_pos[c*64+m]
//
// Pure permutation gather + scalar add; 512MB irreducible traffic.
// R2: 8 independent float4 per thread, all loads front-batched (MLP=8),
// streaming load/store hints. Trading occupancy for per-warp MLP.

__global__ __launch_bounds__(256, 4)
void crosspatch_kernel(const float4* __restrict__ x,
                       const float*  __restrict__ ap,
                       float4*       __restrict__ out)
{
    // Each thread handles 8 float4, stride 256 between them (each access
    // is 32 consecutive float4 per warp -> fully coalesced).
    // Total float4 = 16,777,216 -> 8192 blocks * 256 threads * 8.
    unsigned t0 = blockIdx.x * 2048u + threadIdx.x;

    unsigned src[8];
    float    add[8];

#pragma unroll
    for (int k = 0; k < 8; ++k) {
        unsigned t  = t0 + k * 256u;
        unsigned w4 = t & 127u;          // float4 index within row
        unsigned h  = (t >> 7) & 511u;
        unsigned c  = (t >> 16) & 63u;
        unsigned b  = t >> 22;

        unsigned pw = w4 >> 4;
        unsigned j4 = w4 & 15u;
        unsigned ph = h >> 6;
        unsigned i  = h & 63u;

        unsigned s = ph * 8u + pw;
        unsigned m = (c + s) & 63u;

        unsigned src_h  = ((m >> 3) << 6) | i;
        unsigned src_w4 = ((m & 7u) << 4) | j4;
        unsigned base   = ((b << 6) | c) << 16;   // 65536 float4 per image

        src[k] = base + (src_h << 7) + src_w4;
        add[k] = __ldg(&ap[(c << 6) | m]);
    }

    float4 v[8];
#pragma unroll
    for (int k = 0; k < 8; ++k)
        v[k] = __ldcs(&x[src[k]]);       // evict-first: zero reuse stream

#pragma unroll
    for (int k = 0; k < 8; ++k) {
        float a = add[k];
        v[k].x += a; v[k].y += a; v[k].z += a; v[k].w += a;
        __stcs(&out[t0 + k * 256u], v[k]);
    }
}

extern "C" void kernel_launch(void* const* d_in, const int* in_sizes, int n_in,
                              void* d_out, int out_size)
{
    const float4* x  = (const float4*)d_in[0];   // (4,64,512,512) fp32
    const float*  ap = (const float*)d_in[1];    // (1,1,64,64,1,1) fp32
    float4*       out = (float4*)d_out;

    crosspatch_kernel<<<8192, 256>>>(x, ap, out);
}

// round 5
// speedup vs baseline: 1.0149x; 1.0149x over previous
#include <cuda_runtime.h>
#include <cuda_bf16.h>
#include <cstdint>

// CrossPatchModule closed form (forward):
//   out[b,c,h,w] = x[b,c, (m>>3)*64 + (h&63), (m&7)*64 + (w&63)] + ap[c*64+m]
//   with m = (c + (h>>6)*8 + (w>>6)) & 63
//
// R3: flipped orientation — iterate the SOURCE linearly (sequential,
// prefetch-friendly reads on the latency-exposed path) and scatter the
// stores (latency-insensitive). Inverse map:
//   m = (sh>>6)*8 + (sw>>6);  s = (m - c) & 63
//   dst_h = (s>>3)*64 + (sh&63);  dst_w = (s&7)*64 + (sw&63)
// MLP=4 per thread, occupancy 8 CTAs/SM (R1's optimum), streaming hints.

__global__ __launch_bounds__(256, 8)
void crosspatch_kernel(const float4* __restrict__ x,
                       const float*  __restrict__ ap,
                       float4*       __restrict__ out)
{
    // 4 float4 per thread, stride 256 float4 between them.
    // Total float4 = 16,777,216 -> 16384 blocks * 256 * 4.
    unsigned t0 = blockIdx.x * 1024u + threadIdx.x;

    float4   v[4];
    unsigned dst[4];
    float    add[4];

#pragma unroll
    for (int k = 0; k < 4; ++k) {
        unsigned t = t0 + k * 256u;
        v[k] = __ldcs(&x[t]);            // sequential streaming read
    }

#pragma unroll
    for (int k = 0; k < 4; ++k) {
        unsigned t   = t0 + k * 256u;
        unsigned w4  = t & 127u;         // src float4-col (128 per row)
        unsigned sh  = (t >> 7) & 511u;  // src row
        unsigned c   = (t >> 16) & 63u;
        unsigned b   = t >> 22;

        unsigned m  = ((sh >> 6) << 3) | (w4 >> 4);   // (sh/64)*8 + (sw/64)
        unsigned s  = (m - c) & 63u;
        unsigned i  = sh & 63u;
        unsigned j4 = w4 & 15u;

        unsigned dst_h  = ((s >> 3) << 6) | i;
        unsigned dst_w4 = ((s & 7u) << 4) | j4;
        unsigned base   = ((b << 6) | c) << 16;       // 65536 float4/image

        dst[k] = base + (dst_h << 7) + dst_w4;
        add[k] = __ldg(&ap[(c << 6) | m]);
    }

#pragma unroll
    for (int k = 0; k < 4; ++k) {
        float a = add[k];
        v[k].x += a; v[k].y += a; v[k].z += a; v[k].w += a;
        __stcs(&out[dst[k]], v[k]);       // scattered streaming write
    }
}

extern "C" void kernel_launch(void* const* d_in, const int* in_sizes, int n_in,
                              void* d_out, int out_size)
{
    const float4* x   = (const float4*)d_in[0];   // (4,64,512,512) fp32
    const float*  ap  = (const float*)d_in[1];    // (1,1,64,64,1,1) fp32
    float4*       out = (float4*)d_out;

    crosspatch_kernel<<<16384, 256>>>(x, ap, out);
}